// round 4
// baseline (speedup 1.0000x reference)
#include <cuda_runtime.h>
#include <math.h>

#define B_ 1024
#define N_ 50000
#define D_ 256
#define NV4 (N_ / 4)        // 12500 float4 per row
#define WPR 25              // warps per row: 24 full segs of 512 + 1 seg of 212
#define SEG 512             // float4 per full warp segment
#define P1_TPB 256
#define BCE_BLOCKS (B_ * WPR / 8)   // 3200 blocks for BCE streaming
#define DT_BLOCKS 20                // extra blocks for [B,D] terms
#define P1_GRID (BCE_BLOCKS + DT_BLOCKS)

// Per-row partials: 0..2 sumexp(merged,text,rec), 3..5 dot, 6 sum(x)
__device__ double g_row[B_][7];
// Global scalars: 3 KLD1 sum, 4 KLD2 sum, 5 wasserstein sum (0..2 unused)
__device__ double g_acc[6];

__device__ __forceinline__ float sum_exp4(float4 v) {
    return __expf(v.x) + __expf(v.y) + __expf(v.z) + __expf(v.w);
}
__device__ __forceinline__ float dot4(float4 a, float4 b) {
    return a.x * b.x + a.y * b.y + a.z * b.z + a.w * b.w;
}

// Pass 1: warp-centric, barrier-free streaming reduce over the 3 logits + x,
// plus DT_BLOCKS trailing blocks handling the [B,D] elementwise terms.
__global__ __launch_bounds__(P1_TPB, 4)
void pass1_kernel(const float4* __restrict__ recon,
                  const float4* __restrict__ xmat,
                  const float4* __restrict__ text,
                  const float4* __restrict__ rec,
                  const float*  __restrict__ z,
                  const float*  __restrict__ mu,
                  const float*  __restrict__ lv,
                  const float*  __restrict__ pmu,
                  const float*  __restrict__ plv)
{
    const int lane = threadIdx.x & 31;

    if (blockIdx.x >= BCE_BLOCKS) {
        // ---- [B,D] elementwise terms: KLD1 / KLD2 / Wasserstein ----
        const int n = B_ * D_;
        const int tid0 = (blockIdx.x - BCE_BLOCKS) * P1_TPB + threadIdx.x;
        float k1 = 0.f, k2 = 0.f, wv = 0.f;
        for (int i = tid0; i < n; i += DT_BLOCKS * P1_TPB) {
            float m  = mu[i];
            float l  = lv[i];
            float pm = pmu[i];
            float pl = plv[i];
            float zz = z[i];

            float el  = __expf(l);
            float epl = __expf(pl);

            k1 += 1.f + l - m * m - el;
            float dz = zz - pm;
            k2 += -0.5f * pl - 0.5f * dz * dz * __expf(-pl) + 0.5f * zz * zz;
            float dm = m - pm;
            wv += dm * dm + el + epl - 2.f * sqrtf(el * epl);
        }
        float vals[3] = {k1, k2, wv};
        #pragma unroll
        for (int j = 0; j < 3; j++) {
            float v = vals[j];
            #pragma unroll
            for (int o = 16; o > 0; o >>= 1) v += __shfl_down_sync(0xffffffffu, v, o);
            vals[j] = v;
        }
        if (lane == 0) {
            atomicAdd(&g_acc[3], (double)vals[0]);
            atomicAdd(&g_acc[4], (double)vals[1]);
            atomicAdd(&g_acc[5], (double)vals[2]);
        }
        return;
    }

    // ---- BCE streaming ----
    const int gw   = (blockIdx.x * P1_TPB + threadIdx.x) >> 5;  // global warp id
    const int row  = gw / WPR;
    const int seg  = gw - row * WPR;

    const size_t base = (size_t)row * NV4;
    const float4* __restrict__ R = recon + base;
    const float4* __restrict__ X = xmat  + base;
    const float4* __restrict__ T = text  + base;
    const float4* __restrict__ C = rec   + base;

    float se0 = 0.f, se1 = 0.f, se2 = 0.f;
    float d0 = 0.f, d1 = 0.f, d2 = 0.f;
    float sx = 0.f;

    if (seg < 24) {
        // full 512-float4 segment: 8 unrolled pairs, 8 LDG.128 in flight
        int i = seg * SEG + lane;
        #pragma unroll 1
        for (int p = 0; p < 8; p++, i += 64) {
            float4 r0 = __ldcs(&R[i]);
            float4 x0 = __ldcs(&X[i]);
            float4 t0 = __ldcs(&T[i]);
            float4 c0 = __ldcs(&C[i]);
            float4 r1 = __ldcs(&R[i + 32]);
            float4 x1 = __ldcs(&X[i + 32]);
            float4 t1 = __ldcs(&T[i + 32]);
            float4 c1 = __ldcs(&C[i + 32]);

            se0 += sum_exp4(r0) + sum_exp4(r1);
            se1 += sum_exp4(t0) + sum_exp4(t1);
            se2 += sum_exp4(c0) + sum_exp4(c1);
            d0  += dot4(r0, x0) + dot4(r1, x1);
            d1  += dot4(t0, x0) + dot4(t1, x1);
            d2  += dot4(c0, x0) + dot4(c1, x1);
            sx  += x0.x + x0.y + x0.z + x0.w + x1.x + x1.y + x1.z + x1.w;
        }
    } else {
        // tail segment: columns [12288, 12500) = 212 float4
        for (int i = 24 * SEG + lane; i < NV4; i += 32) {
            float4 r0 = __ldcs(&R[i]);
            float4 x0 = __ldcs(&X[i]);
            float4 t0 = __ldcs(&T[i]);
            float4 c0 = __ldcs(&C[i]);
            se0 += sum_exp4(r0);
            se1 += sum_exp4(t0);
            se2 += sum_exp4(c0);
            d0  += dot4(r0, x0);
            d1  += dot4(t0, x0);
            d2  += dot4(c0, x0);
            sx  += x0.x + x0.y + x0.z + x0.w;
        }
    }

    // Warp reduce 7 scalars, one double atomicAdd each per warp (spread addrs).
    float vals[7] = {se0, se1, se2, d0, d1, d2, sx};
    #pragma unroll
    for (int j = 0; j < 7; j++) {
        float v = vals[j];
        #pragma unroll
        for (int o = 16; o > 0; o >>= 1) v += __shfl_down_sync(0xffffffffu, v, o);
        vals[j] = v;
    }
    if (lane == 0) {
        #pragma unroll
        for (int j = 0; j < 7; j++) atomicAdd(&g_row[row][j], (double)vals[j]);
    }
}

// Finalize: single block, one row per thread. No atomics to hot addresses,
// no fence/counter protocol — stream order guarantees pass1 completion.
__global__ __launch_bounds__(1024)
void finalize_kernel(float* __restrict__ out)
{
    const int t = threadIdx.x;   // 1024 == B_

    double se0 = g_row[t][0], se1 = g_row[t][1], se2 = g_row[t][2];
    double dd0 = g_row[t][3], dd1 = g_row[t][4], dd2 = g_row[t][5];
    double sxd = g_row[t][6];

    // logf on ~8e4-magnitude sums: abs err on lse ~1e-6 -> ~7e-7 rel on BCE.
    double c0 = dd0 - (double)logf((float)se0) * sxd;
    double c1 = dd1 - (double)logf((float)se1) * sxd;
    double c2 = dd2 - (double)logf((float)se2) * sxd;

    // reset this row's partials for the next graph replay
    #pragma unroll
    for (int j = 0; j < 7; j++) g_row[t][j] = 0.0;

    // block reduce 3 doubles across 32 warps
    __shared__ double sh[3][32];
    double vals[3] = {c0, c1, c2};
    const int lane = t & 31;
    const int w    = t >> 5;
    #pragma unroll
    for (int j = 0; j < 3; j++) {
        double v = vals[j];
        #pragma unroll
        for (int o = 16; o > 0; o >>= 1) v += __shfl_down_sync(0xffffffffu, v, o);
        if (lane == 0) sh[j][w] = v;
    }
    __syncthreads();

    if (t == 0) {
        double a0 = 0.0, a1 = 0.0, a2 = 0.0;
        #pragma unroll
        for (int q = 0; q < 32; q++) { a0 += sh[0][q]; a1 += sh[1][q]; a2 += sh[2][q]; }

        double a3 = g_acc[3], a4 = g_acc[4], a5 = g_acc[5];
        g_acc[3] = 0.0; g_acc[4] = 0.0; g_acc[5] = 0.0;

        const double invBN = 1.0 / ((double)B_ * (double)N_);
        const double invBD = 1.0 / ((double)B_ * (double)D_);

        double bce_merged = -a0 * invBN;
        double bce_text   = -a1 * invBN;
        double bce_rec    = -a2 * invBN;
        double BCE = (bce_merged + bce_text + bce_rec) / 3.0;

        double KLD1 = -0.5 * a3 * invBD;
        double KLD2 = a4 * invBD;            // ANNEAL = 1
        double wass = a5 / (double)B_;

        double lval = BCE + 0.5 * (KLD1 + KLD2) + wass;  // ANNEAL/2, EPSILON=1

        out[0] = (float)lval;
        out[1] = (float)BCE;
        out[2] = (float)wass;
        out[3] = (float)bce_rec;
        out[4] = (float)bce_text;
        out[5] = (float)bce_merged;
    }
}

extern "C" void kernel_launch(void* const* d_in, const int* in_sizes, int n_in,
                              void* d_out, int out_size) {
    const float* recon = (const float*)d_in[0];
    const float* x     = (const float*)d_in[1];
    const float* z     = (const float*)d_in[2];
    const float* mu    = (const float*)d_in[3];
    const float* lv    = (const float*)d_in[4];
    const float* text  = (const float*)d_in[5];
    const float* rec   = (const float*)d_in[6];
    const float* pmu   = (const float*)d_in[7];
    const float* plv   = (const float*)d_in[8];
    // d_in[9] = train_items, unused by the loss

    pass1_kernel<<<P1_GRID, P1_TPB>>>((const float4*)recon, (const float4*)x,
                                      (const float4*)text, (const float4*)rec,
                                      z, mu, lv, pmu, plv);
    finalize_kernel<<<1, 1024>>>((float*)d_out);
}

// round 5
// speedup vs baseline: 1.1502x; 1.1502x over previous
#include <cuda_runtime.h>
#include <math.h>

#define B_ 1024
#define N_ 50000
#define D_ 256
#define NV4 (N_ / 4)        // 12500 float4 per row
#define WPR 25              // warps per row: 24 full segs of 512 + 1 seg of 212
#define SEG 512             // float4 per full warp segment
#define P1_TPB 256
#define P1_GRID (B_ * WPR / 8)   // 3200 blocks
#define P2_BLOCKS 32
#define P2_TPB 256

// Per-row partials: 0..2 sumexp(merged,text,rec), 3..5 dot, 6 sum(x)
__device__ double g_row[B_][7];
// Global scalars: 0..2 BCE sums, 3 KLD1 sum, 4 KLD2 sum, 5 wasserstein sum
__device__ double g_acc[6];
__device__ unsigned int g_cnt;

__device__ __forceinline__ float sum_exp4(float4 v) {
    return __expf(v.x) + __expf(v.y) + __expf(v.z) + __expf(v.w);
}
__device__ __forceinline__ float dot4(float4 a, float4 b) {
    return a.x * b.x + a.y * b.y + a.z * b.z + a.w * b.w;
}

// Pass 1 (identical to the proven round-3 kernel): warp-centric, barrier-free
// streaming reduce over the 3 logits matrices + x.
__global__ __launch_bounds__(P1_TPB, 4)
void pass1_kernel(const float4* __restrict__ recon,
                  const float4* __restrict__ xmat,
                  const float4* __restrict__ text,
                  const float4* __restrict__ rec)
{
    const int lane = threadIdx.x & 31;
    const int gw   = (blockIdx.x * P1_TPB + threadIdx.x) >> 5;  // global warp id
    const int row  = gw / WPR;
    const int seg  = gw - row * WPR;

    const size_t base = (size_t)row * NV4;
    const float4* __restrict__ R = recon + base;
    const float4* __restrict__ X = xmat  + base;
    const float4* __restrict__ T = text  + base;
    const float4* __restrict__ C = rec   + base;

    float se0 = 0.f, se1 = 0.f, se2 = 0.f;
    float d0 = 0.f, d1 = 0.f, d2 = 0.f;
    float sx = 0.f;

    if (seg < 24) {
        // full 512-float4 segment: 8 unrolled pairs, 8 LDG.128 in flight
        int i = seg * SEG + lane;
        #pragma unroll 1
        for (int p = 0; p < 8; p++, i += 64) {
            float4 r0 = __ldcs(&R[i]);
            float4 x0 = __ldcs(&X[i]);
            float4 t0 = __ldcs(&T[i]);
            float4 c0 = __ldcs(&C[i]);
            float4 r1 = __ldcs(&R[i + 32]);
            float4 x1 = __ldcs(&X[i + 32]);
            float4 t1 = __ldcs(&T[i + 32]);
            float4 c1 = __ldcs(&C[i + 32]);

            se0 += sum_exp4(r0) + sum_exp4(r1);
            se1 += sum_exp4(t0) + sum_exp4(t1);
            se2 += sum_exp4(c0) + sum_exp4(c1);
            d0  += dot4(r0, x0) + dot4(r1, x1);
            d1  += dot4(t0, x0) + dot4(t1, x1);
            d2  += dot4(c0, x0) + dot4(c1, x1);
            sx  += x0.x + x0.y + x0.z + x0.w + x1.x + x1.y + x1.z + x1.w;
        }
    } else {
        // tail segment: columns [12288, 12500) = 212 float4
        for (int i = 24 * SEG + lane; i < NV4; i += 32) {
            float4 r0 = __ldcs(&R[i]);
            float4 x0 = __ldcs(&X[i]);
            float4 t0 = __ldcs(&T[i]);
            float4 c0 = __ldcs(&C[i]);
            se0 += sum_exp4(r0);
            se1 += sum_exp4(t0);
            se2 += sum_exp4(c0);
            d0  += dot4(r0, x0);
            d1  += dot4(t0, x0);
            d2  += dot4(c0, x0);
            sx  += x0.x + x0.y + x0.z + x0.w;
        }
    }

    // Warp reduce 7 scalars, one double atomicAdd each per warp (spread addrs).
    float vals[7] = {se0, se1, se2, d0, d1, d2, sx};
    #pragma unroll
    for (int j = 0; j < 7; j++) {
        float v = vals[j];
        #pragma unroll
        for (int o = 16; o > 0; o >>= 1) v += __shfl_down_sync(0xffffffffu, v, o);
        vals[j] = v;
    }
    if (lane == 0) {
        #pragma unroll
        for (int j = 0; j < 7; j++) atomicAdd(&g_row[row][j], (double)vals[j]);
    }
}

// Pass 2: 32 blocks. Each block does a slice of the [B,D] dterms (float4),
// warp 0 handles 32 rows' BCE log-corrections, then fence+counter finalize.
__global__ __launch_bounds__(P2_TPB)
void pass2_kernel(const float4* __restrict__ z,
                  const float4* __restrict__ mu,
                  const float4* __restrict__ lv,
                  const float4* __restrict__ pmu,
                  const float4* __restrict__ plv,
                  float* __restrict__ out)
{
    const int t    = threadIdx.x;
    const int lane = t & 31;
    const int w    = t >> 5;
    const int gtid = blockIdx.x * P2_TPB + t;

    // ---- [B,D] elementwise terms over float4 (n4 = 65536) ----
    const int n4 = (B_ * D_) / 4;
    float k1 = 0.f, k2 = 0.f, wv = 0.f;
    for (int i = gtid; i < n4; i += P2_BLOCKS * P2_TPB) {
        float4 m4  = mu[i];
        float4 l4  = lv[i];
        float4 pm4 = pmu[i];
        float4 pl4 = plv[i];
        float4 z4  = z[i];

        #pragma unroll
        for (int q = 0; q < 4; q++) {
            float m  = (&m4.x)[q];
            float l  = (&l4.x)[q];
            float pm = (&pm4.x)[q];
            float pl = (&pl4.x)[q];
            float zz = (&z4.x)[q];

            float el  = __expf(l);
            float epl = __expf(pl);

            k1 += 1.f + l - m * m - el;
            float dz = zz - pm;
            k2 += -0.5f * pl - 0.5f * dz * dz * __expf(-pl) + 0.5f * zz * zz;
            float dm = m - pm;
            wv += dm * dm + el + epl - 2.f * sqrtf(el * epl);
        }
    }

    __shared__ float sh[3][8];
    float vals[3] = {k1, k2, wv};
    #pragma unroll
    for (int j = 0; j < 3; j++) {
        float v = vals[j];
        #pragma unroll
        for (int o = 16; o > 0; o >>= 1) v += __shfl_down_sync(0xffffffffu, v, o);
        if (lane == 0) sh[j][w] = v;
    }
    __syncthreads();

    if (w == 0) {
        // ---- per-row BCE corrections: lane handles row = blockIdx.x*32 + lane ----
        const int row = blockIdx.x * 32 + lane;
        double se0 = g_row[row][0], se1 = g_row[row][1], se2 = g_row[row][2];
        double dd0 = g_row[row][3], dd1 = g_row[row][4], dd2 = g_row[row][5];
        double sxd = g_row[row][6];

        // logf on ~8e4-magnitude sums: ~1e-7 relative on the product, far < 1e-3.
        double c0 = dd0 - (double)logf((float)se0) * sxd;
        double c1 = dd1 - (double)logf((float)se1) * sxd;
        double c2 = dd2 - (double)logf((float)se2) * sxd;

        // reset this row's partials for the next graph replay
        #pragma unroll
        for (int j = 0; j < 7; j++) g_row[row][j] = 0.0;

        // warp reduce three doubles
        #pragma unroll
        for (int o = 16; o > 0; o >>= 1) {
            c0 += __shfl_down_sync(0xffffffffu, c0, o);
            c1 += __shfl_down_sync(0xffffffffu, c1, o);
            c2 += __shfl_down_sync(0xffffffffu, c2, o);
        }

        if (lane == 0) {
            float s0 = 0.f, s1 = 0.f, s2 = 0.f;
            #pragma unroll
            for (int q = 0; q < 8; q++) { s0 += sh[0][q]; s1 += sh[1][q]; s2 += sh[2][q]; }

            atomicAdd(&g_acc[0], c0);
            atomicAdd(&g_acc[1], c1);
            atomicAdd(&g_acc[2], c2);
            atomicAdd(&g_acc[3], (double)s0);
            atomicAdd(&g_acc[4], (double)s1);
            atomicAdd(&g_acc[5], (double)s2);

            __threadfence();
            unsigned done = atomicAdd(&g_cnt, 1u);
            if (done == P2_BLOCKS - 1) {
                double a[6];
                #pragma unroll
                for (int j = 0; j < 6; j++) a[j] = atomicAdd(&g_acc[j], 0.0);

                const double invBN = 1.0 / ((double)B_ * (double)N_);
                const double invBD = 1.0 / ((double)B_ * (double)D_);

                double bce_merged = -a[0] * invBN;
                double bce_text   = -a[1] * invBN;
                double bce_rec    = -a[2] * invBN;
                double BCE = (bce_merged + bce_text + bce_rec) / 3.0;

                double KLD1 = -0.5 * a[3] * invBD;
                double KLD2 = a[4] * invBD;            // ANNEAL = 1
                double wass = a[5] / (double)B_;

                double lval = BCE + 0.5 * (KLD1 + KLD2) + wass;  // ANNEAL/2, EPSILON=1

                out[0] = (float)lval;
                out[1] = (float)BCE;
                out[2] = (float)wass;
                out[3] = (float)bce_rec;
                out[4] = (float)bce_text;
                out[5] = (float)bce_merged;

                #pragma unroll
                for (int j = 0; j < 6; j++) g_acc[j] = 0.0;
                g_cnt = 0u;
            }
        }
    }
}

extern "C" void kernel_launch(void* const* d_in, const int* in_sizes, int n_in,
                              void* d_out, int out_size) {
    const float* recon = (const float*)d_in[0];
    const float* x     = (const float*)d_in[1];
    const float* z     = (const float*)d_in[2];
    const float* mu    = (const float*)d_in[3];
    const float* lv    = (const float*)d_in[4];
    const float* text  = (const float*)d_in[5];
    const float* rec   = (const float*)d_in[6];
    const float* pmu   = (const float*)d_in[7];
    const float* plv   = (const float*)d_in[8];
    // d_in[9] = train_items, unused by the loss

    pass1_kernel<<<P1_GRID, P1_TPB>>>((const float4*)recon, (const float4*)x,
                                      (const float4*)text, (const float4*)rec);
    pass2_kernel<<<P2_BLOCKS, P2_TPB>>>((const float4*)z, (const float4*)mu,
                                        (const float4*)lv, (const float4*)pmu,
                                        (const float4*)plv, (float*)d_out);
}

// round 6
// speedup vs baseline: 1.1982x; 1.0417x over previous
#include <cuda_runtime.h>
#include <math.h>

#define B_ 1024
#define N_ 50000
#define D_ 256
#define NV4 (N_ / 4)        // 12500 float4 per row
#define WPR 25              // warps per row: 24 full segs of 512 + 1 seg of 212
#define SEG 512             // float4 per full warp segment
#define P1_TPB 256
#define P1_GRID (B_ * WPR / 8)   // 3200 blocks
#define P2_BLOCKS 128
#define P2_TPB 256

// Per-row partials: 0..2 sumexp(merged,text,rec), 3..5 dot, 6 sum(x)
__device__ double g_row[B_][7];
// Global scalars: 0..2 BCE sums, 3 KLD1 sum, 4 KLD2 sum, 5 wasserstein sum
__device__ double g_acc[6];
__device__ unsigned int g_cnt;

__device__ __forceinline__ float sum_exp4(float4 v) {
    return __expf(v.x) + __expf(v.y) + __expf(v.z) + __expf(v.w);
}
__device__ __forceinline__ float dot4(float4 a, float4 b) {
    return a.x * b.x + a.y * b.y + a.z * b.z + a.w * b.w;
}

// Pass 1 (byte-identical to the proven round-3 kernel): warp-centric,
// barrier-free streaming reduce over the 3 logits matrices + x.
__global__ __launch_bounds__(P1_TPB, 4)
void pass1_kernel(const float4* __restrict__ recon,
                  const float4* __restrict__ xmat,
                  const float4* __restrict__ text,
                  const float4* __restrict__ rec)
{
    const int lane = threadIdx.x & 31;
    const int gw   = (blockIdx.x * P1_TPB + threadIdx.x) >> 5;  // global warp id
    const int row  = gw / WPR;
    const int seg  = gw - row * WPR;

    const size_t base = (size_t)row * NV4;
    const float4* __restrict__ R = recon + base;
    const float4* __restrict__ X = xmat  + base;
    const float4* __restrict__ T = text  + base;
    const float4* __restrict__ C = rec   + base;

    float se0 = 0.f, se1 = 0.f, se2 = 0.f;
    float d0 = 0.f, d1 = 0.f, d2 = 0.f;
    float sx = 0.f;

    if (seg < 24) {
        // full 512-float4 segment: 8 unrolled pairs, 8 LDG.128 in flight
        int i = seg * SEG + lane;
        #pragma unroll 1
        for (int p = 0; p < 8; p++, i += 64) {
            float4 r0 = __ldcs(&R[i]);
            float4 x0 = __ldcs(&X[i]);
            float4 t0 = __ldcs(&T[i]);
            float4 c0 = __ldcs(&C[i]);
            float4 r1 = __ldcs(&R[i + 32]);
            float4 x1 = __ldcs(&X[i + 32]);
            float4 t1 = __ldcs(&T[i + 32]);
            float4 c1 = __ldcs(&C[i + 32]);

            se0 += sum_exp4(r0) + sum_exp4(r1);
            se1 += sum_exp4(t0) + sum_exp4(t1);
            se2 += sum_exp4(c0) + sum_exp4(c1);
            d0  += dot4(r0, x0) + dot4(r1, x1);
            d1  += dot4(t0, x0) + dot4(t1, x1);
            d2  += dot4(c0, x0) + dot4(c1, x1);
            sx  += x0.x + x0.y + x0.z + x0.w + x1.x + x1.y + x1.z + x1.w;
        }
    } else {
        // tail segment: columns [12288, 12500) = 212 float4
        for (int i = 24 * SEG + lane; i < NV4; i += 32) {
            float4 r0 = __ldcs(&R[i]);
            float4 x0 = __ldcs(&X[i]);
            float4 t0 = __ldcs(&T[i]);
            float4 c0 = __ldcs(&C[i]);
            se0 += sum_exp4(r0);
            se1 += sum_exp4(t0);
            se2 += sum_exp4(c0);
            d0  += dot4(r0, x0);
            d1  += dot4(t0, x0);
            d2  += dot4(c0, x0);
            sx  += x0.x + x0.y + x0.z + x0.w;
        }
    }

    // Warp reduce 7 scalars, one double atomicAdd each per warp (spread addrs).
    float vals[7] = {se0, se1, se2, d0, d1, d2, sx};
    #pragma unroll
    for (int j = 0; j < 7; j++) {
        float v = vals[j];
        #pragma unroll
        for (int o = 16; o > 0; o >>= 1) v += __shfl_down_sync(0xffffffffu, v, o);
        vals[j] = v;
    }
    if (lane == 0) {
        #pragma unroll
        for (int j = 0; j < 7; j++) atomicAdd(&g_row[row][j], (double)vals[j]);
    }
}

// Pass 2: 128 blocks x 256 threads. Each thread handles exactly 2 float4 of
// the [B,D] dterms (full-chip BW); warp 0 of blocks 0..31 handles 32 rows'
// BCE log-corrections each; fence+counter; last block finalizes + resets.
__global__ __launch_bounds__(P2_TPB)
void pass2_kernel(const float4* __restrict__ z,
                  const float4* __restrict__ mu,
                  const float4* __restrict__ lv,
                  const float4* __restrict__ pmu,
                  const float4* __restrict__ plv,
                  float* __restrict__ out)
{
    const int t    = threadIdx.x;
    const int lane = t & 31;
    const int w    = t >> 5;
    const int gtid = blockIdx.x * P2_TPB + t;
    const int NT   = P2_BLOCKS * P2_TPB;   // 32768 threads; n4 = 65536

    // ---- [B,D] elementwise terms: exactly 2 float4 per thread, fully unrolled ----
    float k1 = 0.f, k2 = 0.f, wv = 0.f;
    #pragma unroll
    for (int rep = 0; rep < 2; rep++) {
        const int i = gtid + rep * NT;
        float4 m4  = mu[i];
        float4 l4  = lv[i];
        float4 pm4 = pmu[i];
        float4 pl4 = plv[i];
        float4 z4  = z[i];

        #pragma unroll
        for (int q = 0; q < 4; q++) {
            float m  = (&m4.x)[q];
            float l  = (&l4.x)[q];
            float pm = (&pm4.x)[q];
            float pl = (&pl4.x)[q];
            float zz = (&z4.x)[q];

            float el  = __expf(l);
            float epl = __expf(pl);

            k1 += 1.f + l - m * m - el;
            float dz = zz - pm;
            k2 += -0.5f * pl - 0.5f * dz * dz * __expf(-pl) + 0.5f * zz * zz;
            float dm = m - pm;
            wv += dm * dm + el + epl - 2.f * sqrtf(el * epl);
        }
    }

    __shared__ float sh[3][8];
    float vals[3] = {k1, k2, wv};
    #pragma unroll
    for (int j = 0; j < 3; j++) {
        float v = vals[j];
        #pragma unroll
        for (int o = 16; o > 0; o >>= 1) v += __shfl_down_sync(0xffffffffu, v, o);
        if (lane == 0) sh[j][w] = v;
    }
    __syncthreads();

    if (w == 0) {
        double c0 = 0.0, c1 = 0.0, c2 = 0.0;
        if (blockIdx.x < 32) {
            // ---- per-row BCE corrections: row = blockIdx.x*32 + lane ----
            const int row = blockIdx.x * 32 + lane;
            double se0 = g_row[row][0], se1 = g_row[row][1], se2 = g_row[row][2];
            double dd0 = g_row[row][3], dd1 = g_row[row][4], dd2 = g_row[row][5];
            double sxd = g_row[row][6];

            // logf on ~8e4-magnitude sums: ~1e-7 relative error, far < 1e-3.
            c0 = dd0 - (double)logf((float)se0) * sxd;
            c1 = dd1 - (double)logf((float)se1) * sxd;
            c2 = dd2 - (double)logf((float)se2) * sxd;

            // reset this row's partials for the next graph replay
            #pragma unroll
            for (int j = 0; j < 7; j++) g_row[row][j] = 0.0;

            #pragma unroll
            for (int o = 16; o > 0; o >>= 1) {
                c0 += __shfl_down_sync(0xffffffffu, c0, o);
                c1 += __shfl_down_sync(0xffffffffu, c1, o);
                c2 += __shfl_down_sync(0xffffffffu, c2, o);
            }
        }

        if (lane == 0) {
            float s0 = 0.f, s1 = 0.f, s2 = 0.f;
            #pragma unroll
            for (int q = 0; q < 8; q++) { s0 += sh[0][q]; s1 += sh[1][q]; s2 += sh[2][q]; }

            if (blockIdx.x < 32) {
                atomicAdd(&g_acc[0], c0);
                atomicAdd(&g_acc[1], c1);
                atomicAdd(&g_acc[2], c2);
            }
            atomicAdd(&g_acc[3], (double)s0);
            atomicAdd(&g_acc[4], (double)s1);
            atomicAdd(&g_acc[5], (double)s2);

            __threadfence();
            unsigned done = atomicAdd(&g_cnt, 1u);
            if (done == P2_BLOCKS - 1) {
                double a[6];
                #pragma unroll
                for (int j = 0; j < 6; j++) a[j] = atomicAdd(&g_acc[j], 0.0);

                const double invBN = 1.0 / ((double)B_ * (double)N_);
                const double invBD = 1.0 / ((double)B_ * (double)D_);

                double bce_merged = -a[0] * invBN;
                double bce_text   = -a[1] * invBN;
                double bce_rec    = -a[2] * invBN;
                double BCE = (bce_merged + bce_text + bce_rec) / 3.0;

                double KLD1 = -0.5 * a[3] * invBD;
                double KLD2 = a[4] * invBD;            // ANNEAL = 1
                double wass = a[5] / (double)B_;

                double lval = BCE + 0.5 * (KLD1 + KLD2) + wass;  // ANNEAL/2, EPSILON=1

                out[0] = (float)lval;
                out[1] = (float)BCE;
                out[2] = (float)wass;
                out[3] = (float)bce_rec;
                out[4] = (float)bce_text;
                out[5] = (float)bce_merged;

                #pragma unroll
                for (int j = 0; j < 6; j++) g_acc[j] = 0.0;
                g_cnt = 0u;
            }
        }
    }
}

extern "C" void kernel_launch(void* const* d_in, const int* in_sizes, int n_in,
                              void* d_out, int out_size) {
    const float* recon = (const float*)d_in[0];
    const float* x     = (const float*)d_in[1];
    const float* z     = (const float*)d_in[2];
    const float* mu    = (const float*)d_in[3];
    const float* lv    = (const float*)d_in[4];
    const float* text  = (const float*)d_in[5];
    const float* rec   = (const float*)d_in[6];
    const float* pmu   = (const float*)d_in[7];
    const float* plv   = (const float*)d_in[8];
    // d_in[9] = train_items, unused by the loss

    pass1_kernel<<<P1_GRID, P1_TPB>>>((const float4*)recon, (const float4*)x,
                                      (const float4*)text, (const float4*)rec);
    pass2_kernel<<<P2_BLOCKS, P2_TPB>>>((const float4*)z, (const float4*)mu,
                                        (const float4*)lv, (const float4*)pmu,
                                        (const float4*)plv, (float*)d_out);
}